// round 11
// baseline (speedup 1.0000x reference)
#include <cuda_runtime.h>
#include <math.h>

#define NROWS   12800     // B*C
#define BATCH   256
#define CDIM    50
#define INPUT   128
#define INTER   64
#define HIDDEN  128
#define NSLOT   11
#define USTRIDE (NSLOT * INTER)      // 704
#define NCHUNK  32
#define RPC     (NROWS / NCHUNK)     // 400 rows per chunk
#define NROUND  13                   // 11 dw slots + 2 hw halves
#define BPG     8                    // batches per stage2 CTA-group
#define NB      (NCHUNK * NROUND)    // 416 CTAs (<= 148 SMs x 3 -> co-resident)

// Bucketed accumulator u[b][dist_slot][j]. Zero-init at load; phase2 CTA that
// consumes each slot rezeroes it -> replay-safe without a zero kernel.
__device__ float g_u[BATCH * USTRIDE];
// Pre-sigmoid output accumulator. Zero-init; finisher rezeroes after reading.
__device__ float g_acc[BATCH * HIDDEN];
// Monotonic grid-barrier counter and per-bx finisher counters (never reset).
__device__ unsigned g_bar;
__device__ unsigned g_fin[NCHUNK];

__global__ __launch_bounds__(256, 3) void fused_kernel(
    const float* __restrict__ x,     // (B,C,INPUT)
    const int* __restrict__ tc,      // (B,C)
    const int* __restrict__ dc,      // (B,C)
    const int* __restrict__ mask,    // (B,C) bool->int32
    const float* __restrict__ h,     // (B,HIDDEN)
    const float* __restrict__ tw,    // (NSLOT,INPUT,INTER)
    const float* __restrict__ dw,    // (NSLOT,INTER,HIDDEN)
    const float* __restrict__ hw,    // (HIDDEN,HIDDEN)
    float* __restrict__ out)         // (B,HIDDEN)
{
    // __align__(16): every float4-cast access below (tws, ws, as) requires
    // 16B alignment; shared placement otherwise only guarantees 4B.
    __shared__ __align__(16) union {
        struct {                          // phase 1
            float tws[INPUT * INTER];     // 32 KB (16B-aligned at offset 0)
            int   list[RPC];
            int   cnt;
            int   pad[3];                 // pad struct to 16B multiple
        } p1;
        float ws[64 * HIDDEN];            // phase 2: W round, 32 KB
    } sh;
    __shared__ __align__(16) float as[BPG * 64];   // 2 KB: A slice, 8 batches
    __shared__ int flag;

    const int id  = blockIdx.x;           // 0..415
    const int t   = threadIdx.x;
    const int bx  = id & 31;              // 0..31  (phase2 batch group)
    const int r   = id >> 5;              // 0..12  (phase2 k-round; ==slot s in phase1)
    const int bbase = bx * BPG;

    // ======================= PHASE 1: x @ tw[s] ===========================
    if (id < NSLOT * NCHUNK) {            // 352 CTAs active
        const int s  = r;                 // 0..10
        const int r0 = bx * RPC;

        if (t == 0) sh.p1.cnt = 0;
        {
            const float4* src = (const float4*)(tw + (size_t)s * INPUT * INTER);
            #pragma unroll 4
            for (int i = t; i < (INPUT * INTER) / 4; i += 256)
                ((float4*)sh.p1.tws)[i] = src[i];
        }
        __syncthreads();

        for (int i = t; i < RPC; i += 256) {
            int rr = r0 + i;
            if (tc[rr] == s && mask[rr] != 0) {
                int pos = atomicAdd(&sh.p1.cnt, 1);
                sh.p1.list[pos] = (dc[rr] << 16) | rr;
            }
        }
        __syncthreads();

        const int n    = sh.p1.cnt;
        const int warp = t >> 5;
        const int lane = t & 31;
        const int j0   = lane * 2;

        for (int i = warp * 2; i < n; i += 16) {
            const int  e0   = sh.p1.list[i];
            const bool has2 = (i + 1) < n;
            const int  e1   = has2 ? sh.p1.list[i + 1] : e0;
            const int  ra   = e0 & 0xFFFF, da = e0 >> 16;
            const int  rb   = e1 & 0xFFFF, db = e1 >> 16;
            const float* xa = x + (size_t)ra * INPUT;
            const float* xb = x + (size_t)rb * INPUT;

            float a0 = 0.f, a1 = 0.f, b0 = 0.f, b1 = 0.f;
            #pragma unroll 8
            for (int k = 0; k < INPUT; k += 4) {
                float4 va = *(const float4*)(xa + k);   // broadcast
                float4 vb = *(const float4*)(xb + k);
                float2 w0 = *(const float2*)(sh.p1.tws + (k + 0) * INTER + j0);
                float2 w1 = *(const float2*)(sh.p1.tws + (k + 1) * INTER + j0);
                float2 w2 = *(const float2*)(sh.p1.tws + (k + 2) * INTER + j0);
                float2 w3 = *(const float2*)(sh.p1.tws + (k + 3) * INTER + j0);
                a0 = fmaf(va.x, w0.x, a0);  a1 = fmaf(va.x, w0.y, a1);
                b0 = fmaf(vb.x, w0.x, b0);  b1 = fmaf(vb.x, w0.y, b1);
                a0 = fmaf(va.y, w1.x, a0);  a1 = fmaf(va.y, w1.y, a1);
                b0 = fmaf(vb.y, w1.x, b0);  b1 = fmaf(vb.y, w1.y, b1);
                a0 = fmaf(va.z, w2.x, a0);  a1 = fmaf(va.z, w2.y, a1);
                b0 = fmaf(vb.z, w2.x, b0);  b1 = fmaf(vb.z, w2.y, b1);
                a0 = fmaf(va.w, w3.x, a0);  a1 = fmaf(va.w, w3.y, a1);
                b0 = fmaf(vb.w, w3.x, b0);  b1 = fmaf(vb.w, w3.y, b1);
            }

            float* ua = g_u + (size_t)(ra / CDIM) * USTRIDE + da * INTER + j0;
            atomicAdd(ua,     a0);
            atomicAdd(ua + 1, a1);
            if (has2) {
                float* ub = g_u + (size_t)(rb / CDIM) * USTRIDE + db * INTER + j0;
                atomicAdd(ub,     b0);
                atomicAdd(ub + 1, b1);
            }
        }
    }
    __syncthreads();   // all warps done reading p1 smem before ws overwrite

    // ===== Pre-barrier prefetch of phase-2 inputs (no stage1 dependency) ===
    {   // W round -> smem (overwrites tws; own CTA is done with it)
        const float* wsrc = (r < NSLOT)
            ? dw + (size_t)r * 64 * HIDDEN
            : hw + (size_t)(r - NSLOT) * 64 * HIDDEN;
        const float4* src = (const float4*)wsrc;
        #pragma unroll
        for (int i = 0; i < 8; i++)
            ((float4*)sh.ws)[t + i * 256] = src[t + i * 256];
    }
    if (r >= NSLOT) {   // h-rounds: whole A slice is launch input
        #pragma unroll
        for (int i = 0; i < 2; i++) {
            int idx = t + i * 256;
            int bb = idx >> 6, j = idx & 63;
            as[idx] = h[(size_t)(bbase + bb) * HIDDEN + (r - NSLOT) * 64 + j];
        }
    }

    // ======================= GRID BARRIER =================================
    // Safe: launch_bounds(256,3) + 34.6KB smem guarantee >=3 CTAs/SM, and
    // NB=416 <= 148*3, so all CTAs are co-resident. Counter is monotonic
    // (never reset) -> correct on the eager call and every graph replay.
    __syncthreads();
    if (t == 0) {
        __threadfence();   // publish g_u atomics before arrival
        unsigned c = atomicAdd(&g_bar, 1u);
        unsigned target = (c / NB + 1u) * NB;
        while (*(volatile unsigned*)&g_bar < target) __nanosleep(64);
        __threadfence();
    }
    __syncthreads();

    // ======================= PHASE 2: flat K-split GEMM ===================
    if (r < NSLOT) {   // u-rounds: read + rezero g_u (each element once)
        #pragma unroll
        for (int i = 0; i < 2; i++) {
            int idx = t + i * 256;
            int bb = idx >> 6, j = idx & 63;
            float* up = g_u + (size_t)(bbase + bb) * USTRIDE + r * 64 + j;
            float v = *up;
            *up = 0.f;
            as[idx] = v;
        }
        __syncthreads();
    }

    const int bg  = t >> 7;     // 0..1
    const int hid = t & 127;

    float acc0 = 0.f, acc1 = 0.f, acc2 = 0.f, acc3 = 0.f;
    #pragma unroll
    for (int j = 0; j < 64; j += 4) {
        float w0 = sh.ws[(j + 0) * HIDDEN + hid];   // conflict-free
        float w1 = sh.ws[(j + 1) * HIDDEN + hid];
        float w2 = sh.ws[(j + 2) * HIDDEN + hid];
        float w3 = sh.ws[(j + 3) * HIDDEN + hid];
        float4 a0 = *(const float4*)(as + (bg + 0) * 64 + j);   // broadcast
        float4 a1 = *(const float4*)(as + (bg + 2) * 64 + j);
        float4 a2 = *(const float4*)(as + (bg + 4) * 64 + j);
        float4 a3 = *(const float4*)(as + (bg + 6) * 64 + j);
        acc0 = fmaf(a0.x, w0, acc0);  acc1 = fmaf(a1.x, w0, acc1);
        acc2 = fmaf(a2.x, w0, acc2);  acc3 = fmaf(a3.x, w0, acc3);
        acc0 = fmaf(a0.y, w1, acc0);  acc1 = fmaf(a1.y, w1, acc1);
        acc2 = fmaf(a2.y, w1, acc2);  acc3 = fmaf(a3.y, w1, acc3);
        acc0 = fmaf(a0.z, w2, acc0);  acc1 = fmaf(a1.z, w2, acc1);
        acc2 = fmaf(a2.z, w2, acc2);  acc3 = fmaf(a3.z, w2, acc3);
        acc0 = fmaf(a0.w, w3, acc0);  acc1 = fmaf(a1.w, w3, acc1);
        acc2 = fmaf(a2.w, w3, acc2);  acc3 = fmaf(a3.w, w3, acc3);
    }

    atomicAdd(g_acc + (size_t)(bbase + bg + 0) * HIDDEN + hid, acc0);
    atomicAdd(g_acc + (size_t)(bbase + bg + 2) * HIDDEN + hid, acc1);
    atomicAdd(g_acc + (size_t)(bbase + bg + 4) * HIDDEN + hid, acc2);
    atomicAdd(g_acc + (size_t)(bbase + bg + 6) * HIDDEN + hid, acc3);

    // Finisher election: 13th-arriving CTA for this bx.
    __threadfence();
    __syncthreads();
    if (t == 0) {
        unsigned c = atomicAdd(&g_fin[bx], 1u);
        flag = ((c % (unsigned)NROUND) == (unsigned)(NROUND - 1)) ? 1 : 0;
    }
    __syncthreads();

    if (flag) {
        #pragma unroll
        for (int i = 0; i < 4; i++) {
            float* p = g_acc + (size_t)(bbase + bg + 2 * i) * HIDDEN + hid;
            float v = __ldcg(p);
            out[(size_t)(bbase + bg + 2 * i) * HIDDEN + hid] =
                1.f / (1.f + expf(-v));
            *p = 0.f;   // rezero for next launch/replay
        }
    }
}

// ---------------------------------------------------------------------------
// kernel_launch: ONE launch (graph-capturable, alloc-free)
// ---------------------------------------------------------------------------
extern "C" void kernel_launch(void* const* d_in, const int* in_sizes, int n_in,
                              void* d_out, int out_size) {
    const float* x    = (const float*)d_in[0];
    const int*   tc   = (const int*)d_in[1];
    const int*   dc   = (const int*)d_in[2];
    const int*   mask = (const int*)d_in[3];
    const float* h    = (const float*)d_in[4];
    const float* tw   = (const float*)d_in[5];
    const float* dw   = (const float*)d_in[6];
    const float* hw   = (const float*)d_in[7];
    float*       out  = (float*)d_out;

    fused_kernel<<<NB, 256>>>(x, tc, dc, mask, h, tw, dw, hw, out);
}

// round 12
// speedup vs baseline: 1.0951x; 1.0951x over previous
#include <cuda_runtime.h>
#include <math.h>

#define NROWS   12800     // B*C
#define BATCH   256
#define CDIM    50
#define INPUT   128
#define INTER   64
#define HIDDEN  128
#define NSLOT   11
#define USTRIDE (NSLOT * INTER)      // 704
#define NCHUNK  32
#define RPC     (NROWS / NCHUNK)     // 400 rows per chunk
#define NROUND  13                   // 11 dw slots + 2 hw halves
#define BPG     8                    // batches per stage2 CTA-group
#define NB      (NCHUNK * NROUND)    // 416 CTAs (<= 148 SMs x 3 -> co-resident)

// Bucketed accumulator u[b][dist_slot][j]. Zero-init at load; phase2 CTA that
// consumes each slot rezeroes it -> replay-safe without a zero kernel.
__device__ float g_u[BATCH * USTRIDE];
// Pre-sigmoid output accumulator. Zero-init; finisher rezeroes after reading.
__device__ float g_acc[BATCH * HIDDEN];
// Monotonic grid-barrier counter and per-bx finisher counters (never reset).
__device__ unsigned g_bar;
__device__ unsigned g_fin[NCHUNK];

__global__ __launch_bounds__(256, 3) void fused_kernel(
    const float* __restrict__ x,     // (B,C,INPUT)
    const int* __restrict__ tc,      // (B,C)
    const int* __restrict__ dc,      // (B,C)
    const int* __restrict__ mask,    // (B,C) bool->int32
    const float* __restrict__ h,     // (B,HIDDEN)
    const float* __restrict__ tw,    // (NSLOT,INPUT,INTER)
    const float* __restrict__ dw,    // (NSLOT,INTER,HIDDEN)
    const float* __restrict__ hw,    // (HIDDEN,HIDDEN)
    float* __restrict__ out)         // (B,HIDDEN)
{
    // __align__(16): float4-cast accesses (tws, xs, ws, as) need 16B alignment.
    __shared__ __align__(16) union {
        struct {                           // phase 1
            float tws[INPUT * INTER];      // 32 KB
            float xs[8][2 * INPUT];        // 8 KB: per-warp staged row pair
            int   list[RPC];
            int   cnt;
            int   pad[3];
        } p1;
        float ws[64 * HIDDEN];             // phase 2: W round, 32 KB
    } sh;
    __shared__ __align__(16) float as[BPG * 64];   // 2 KB: A slice, 8 batches
    __shared__ int flag;

    const int id  = blockIdx.x;            // 0..415
    const int t   = threadIdx.x;
    const int bx  = id & 31;               // 0..31  (phase2 batch group)
    const int r   = id >> 5;               // 0..12  (phase2 k-round; ==slot s in phase1)
    const int bbase = bx * BPG;

    // ======================= PHASE 1: x @ tw[s] ===========================
    if (id < NSLOT * NCHUNK) {             // 352 CTAs active
        const int s  = r;                  // 0..10
        const int r0 = bx * RPC;

        if (t == 0) sh.p1.cnt = 0;
        {
            const float4* src = (const float4*)(tw + (size_t)s * INPUT * INTER);
            #pragma unroll 4
            for (int i = t; i < (INPUT * INTER) / 4; i += 256)
                ((float4*)sh.p1.tws)[i] = src[i];
        }
        __syncthreads();

        for (int i = t; i < RPC; i += 256) {
            int rr = r0 + i;
            if (tc[rr] == s && mask[rr] != 0) {
                int pos = atomicAdd(&sh.p1.cnt, 1);
                sh.p1.list[pos] = (dc[rr] << 16) | rr;
            }
        }
        __syncthreads();

        const int n    = sh.p1.cnt;
        const int warp = t >> 5;
        const int lane = t & 31;
        const int j0   = lane * 2;
        float* xsa = sh.p1.xs[warp];          // row A staging (128 floats)
        float* xsb = sh.p1.xs[warp] + INPUT;  // row B staging

        for (int i = warp * 2; i < n; i += 16) {
            const int  e0   = sh.p1.list[i];
            const bool has2 = (i + 1) < n;
            const int  e1   = has2 ? sh.p1.list[i + 1] : e0;
            const int  ra   = e0 & 0xFFFF, da = e0 >> 16;
            const int  rb   = e1 & 0xFFFF, db = e1 >> 16;

            // Stage both x rows into smem: ONE coalesced LDG.128 per row per
            // lane replaces 64 serialized warp-uniform gmem broadcasts.
            __syncwarp();   // prior iteration's readers done with xs
            {
                float4 va = ((const float4*)(x + (size_t)ra * INPUT))[lane];
                float4 vb = ((const float4*)(x + (size_t)rb * INPUT))[lane];
                *(float4*)(xsa + lane * 4) = va;
                *(float4*)(xsb + lane * 4) = vb;
            }
            __syncwarp();   // staging visible to all lanes

            float a0 = 0.f, a1 = 0.f, b0 = 0.f, b1 = 0.f;
            #pragma unroll 8
            for (int k = 0; k < INPUT; k += 4) {
                float4 va = *(const float4*)(xsa + k);   // smem broadcast
                float4 vb = *(const float4*)(xsb + k);
                float2 w0 = *(const float2*)(sh.p1.tws + (k + 0) * INTER + j0);
                float2 w1 = *(const float2*)(sh.p1.tws + (k + 1) * INTER + j0);
                float2 w2 = *(const float2*)(sh.p1.tws + (k + 2) * INTER + j0);
                float2 w3 = *(const float2*)(sh.p1.tws + (k + 3) * INTER + j0);
                a0 = fmaf(va.x, w0.x, a0);  a1 = fmaf(va.x, w0.y, a1);
                b0 = fmaf(vb.x, w0.x, b0);  b1 = fmaf(vb.x, w0.y, b1);
                a0 = fmaf(va.y, w1.x, a0);  a1 = fmaf(va.y, w1.y, a1);
                b0 = fmaf(vb.y, w1.x, b0);  b1 = fmaf(vb.y, w1.y, b1);
                a0 = fmaf(va.z, w2.x, a0);  a1 = fmaf(va.z, w2.y, a1);
                b0 = fmaf(vb.z, w2.x, b0);  b1 = fmaf(vb.z, w2.y, b1);
                a0 = fmaf(va.w, w3.x, a0);  a1 = fmaf(va.w, w3.y, a1);
                b0 = fmaf(vb.w, w3.x, b0);  b1 = fmaf(vb.w, w3.y, b1);
            }

            float* ua = g_u + (size_t)(ra / CDIM) * USTRIDE + da * INTER + j0;
            atomicAdd(ua,     a0);
            atomicAdd(ua + 1, a1);
            if (has2) {
                float* ub = g_u + (size_t)(rb / CDIM) * USTRIDE + db * INTER + j0;
                atomicAdd(ub,     b0);
                atomicAdd(ub + 1, b1);
            }
        }
    }
    __syncthreads();   // all warps done reading p1 smem before ws overwrite

    // ===== Pre-barrier prefetch of phase-2 inputs (no stage1 dependency) ===
    {   // W round -> smem (overwrites tws; own CTA is done with it)
        const float* wsrc = (r < NSLOT)
            ? dw + (size_t)r * 64 * HIDDEN
            : hw + (size_t)(r - NSLOT) * 64 * HIDDEN;
        const float4* src = (const float4*)wsrc;
        #pragma unroll
        for (int i = 0; i < 8; i++)
            ((float4*)sh.ws)[t + i * 256] = src[t + i * 256];
    }
    if (r >= NSLOT) {   // h-rounds: whole A slice is launch input
        #pragma unroll
        for (int i = 0; i < 2; i++) {
            int idx = t + i * 256;
            int bb = idx >> 6, j = idx & 63;
            as[idx] = h[(size_t)(bbase + bb) * HIDDEN + (r - NSLOT) * 64 + j];
        }
    }

    // ======================= GRID BARRIER =================================
    // Safe: launch_bounds(256,3) + 44.6KB smem guarantee >=3 CTAs/SM, and
    // NB=416 <= 148*3 -> co-resident. Counter monotonic (never reset).
    __syncthreads();
    if (t == 0) {
        __threadfence();   // publish g_u atomics before arrival
        unsigned c = atomicAdd(&g_bar, 1u);
        unsigned target = (c / NB + 1u) * NB;
        while (*(volatile unsigned*)&g_bar < target) __nanosleep(64);
        __threadfence();
    }
    __syncthreads();

    // ======================= PHASE 2: flat K-split GEMM ===================
    if (r < NSLOT) {   // u-rounds: read + rezero g_u (each element once)
        #pragma unroll
        for (int i = 0; i < 2; i++) {
            int idx = t + i * 256;
            int bb = idx >> 6, j = idx & 63;
            float* up = g_u + (size_t)(bbase + bb) * USTRIDE + r * 64 + j;
            float v = *up;
            *up = 0.f;
            as[idx] = v;
        }
        __syncthreads();
    }

    const int bg  = t >> 7;     // 0..1
    const int hid = t & 127;

    float acc0 = 0.f, acc1 = 0.f, acc2 = 0.f, acc3 = 0.f;
    #pragma unroll
    for (int j = 0; j < 64; j += 4) {
        float w0 = sh.ws[(j + 0) * HIDDEN + hid];   // conflict-free
        float w1 = sh.ws[(j + 1) * HIDDEN + hid];
        float w2 = sh.ws[(j + 2) * HIDDEN + hid];
        float w3 = sh.ws[(j + 3) * HIDDEN + hid];
        float4 a0 = *(const float4*)(as + (bg + 0) * 64 + j);   // broadcast
        float4 a1 = *(const float4*)(as + (bg + 2) * 64 + j);
        float4 a2 = *(const float4*)(as + (bg + 4) * 64 + j);
        float4 a3 = *(const float4*)(as + (bg + 6) * 64 + j);
        acc0 = fmaf(a0.x, w0, acc0);  acc1 = fmaf(a1.x, w0, acc1);
        acc2 = fmaf(a2.x, w0, acc2);  acc3 = fmaf(a3.x, w0, acc3);
        acc0 = fmaf(a0.y, w1, acc0);  acc1 = fmaf(a1.y, w1, acc1);
        acc2 = fmaf(a2.y, w1, acc2);  acc3 = fmaf(a3.y, w1, acc3);
        acc0 = fmaf(a0.z, w2, acc0);  acc1 = fmaf(a1.z, w2, acc1);
        acc2 = fmaf(a2.z, w2, acc2);  acc3 = fmaf(a3.z, w2, acc3);
        acc0 = fmaf(a0.w, w3, acc0);  acc1 = fmaf(a1.w, w3, acc1);
        acc2 = fmaf(a2.w, w3, acc2);  acc3 = fmaf(a3.w, w3, acc3);
    }

    atomicAdd(g_acc + (size_t)(bbase + bg + 0) * HIDDEN + hid, acc0);
    atomicAdd(g_acc + (size_t)(bbase + bg + 2) * HIDDEN + hid, acc1);
    atomicAdd(g_acc + (size_t)(bbase + bg + 4) * HIDDEN + hid, acc2);
    atomicAdd(g_acc + (size_t)(bbase + bg + 6) * HIDDEN + hid, acc3);

    // Finisher election: 13th-arriving CTA for this bx.
    __threadfence();
    __syncthreads();
    if (t == 0) {
        unsigned c = atomicAdd(&g_fin[bx], 1u);
        flag = ((c % (unsigned)NROUND) == (unsigned)(NROUND - 1)) ? 1 : 0;
    }
    __syncthreads();

    if (flag) {
        #pragma unroll
        for (int i = 0; i < 4; i++) {
            float* p = g_acc + (size_t)(bbase + bg + 2 * i) * HIDDEN + hid;
            float v = __ldcg(p);
            out[(size_t)(bbase + bg + 2 * i) * HIDDEN + hid] =
                1.f / (1.f + expf(-v));
            *p = 0.f;   // rezero for next launch/replay
        }
    }
}

// ---------------------------------------------------------------------------
// kernel_launch: ONE launch (graph-capturable, alloc-free)
// ---------------------------------------------------------------------------
extern "C" void kernel_launch(void* const* d_in, const int* in_sizes, int n_in,
                              void* d_out, int out_size) {
    const float* x    = (const float*)d_in[0];
    const int*   tc   = (const int*)d_in[1];
    const int*   dc   = (const int*)d_in[2];
    const int*   mask = (const int*)d_in[3];
    const float* h    = (const float*)d_in[4];
    const float* tw   = (const float*)d_in[5];
    const float* dw   = (const float*)d_in[6];
    const float* hw   = (const float*)d_in[7];
    float*       out  = (float*)d_out;

    fused_kernel<<<NB, 256>>>(x, tc, dc, mask, h, tw, dw, hw, out);
}

// round 14
// speedup vs baseline: 1.1719x; 1.0702x over previous
#include <cuda_runtime.h>
#include <math.h>

#define NROWS   12800     // B*C
#define BATCH   256
#define CDIM    50
#define INPUT   128
#define INTER   64
#define HIDDEN  128
#define NSLOT   11
#define USTRIDE (NSLOT * INTER)      // 704
#define NCHUNK  32
#define RPC     (NROWS / NCHUNK)     // 400 rows per chunk
#define NROUND  13                   // 11 dw slots + 2 hw halves
#define BPG     8                    // batches per stage2 CTA-group
#define NB      (NCHUNK * NROUND)    // 416 CTAs (<= 148 SMs x 3 -> co-resident)

// Dynamic smem layout (bytes):
//   phase 1:  [0,32768) tws   [32768,49152) xs (8 warps x 4 rows x 128 f)
//             [49152,50752) list[400]   [50752,50756) cnt
//   phase 2:  [0,32768) ws    [32768,34816) as
#define SM_TWS   0
#define SM_XS    32768
#define SM_LIST  49152
#define SM_CNT   50752
#define SM_WS    0
#define SM_AS    32768
#define SMEM_TOTAL 50768

__device__ float g_u[BATCH * USTRIDE];   // zero-init; phase2 rezeroes after read
__device__ float g_acc[BATCH * HIDDEN];  // zero-init; finisher rezeroes
__device__ unsigned g_bar;               // monotonic, never reset
__device__ unsigned g_fin[NCHUNK];       // monotonic, never reset

__global__ __launch_bounds__(256, 3) void fused_kernel(
    const float* __restrict__ x,     // (B,C,INPUT)
    const int* __restrict__ tc,      // (B,C)
    const int* __restrict__ dc,      // (B,C)
    const int* __restrict__ mask,    // (B,C) bool->int32
    const float* __restrict__ h,     // (B,HIDDEN)
    const float* __restrict__ tw,    // (NSLOT,INPUT,INTER)
    const float* __restrict__ dw,    // (NSLOT,INTER,HIDDEN)
    const float* __restrict__ hw,    // (HIDDEN,HIDDEN)
    float* __restrict__ out)         // (B,HIDDEN)
{
    extern __shared__ __align__(16) char smem[];
    float* tws  = (float*)(smem + SM_TWS);
    int*   list = (int*)(smem + SM_LIST);
    int*   cntp = (int*)(smem + SM_CNT);
    float* ws   = (float*)(smem + SM_WS);
    float* as   = (float*)(smem + SM_AS);
    __shared__ int flag;

    const int id  = blockIdx.x;            // 0..415
    const int t   = threadIdx.x;
    const int bx  = id & 31;
    const int r   = id >> 5;
    const int bbase = bx * BPG;

    // ======================= PHASE 1: x @ tw[s] ===========================
    if (id < NSLOT * NCHUNK) {
        const int s  = r;
        const int r0 = bx * RPC;

        if (t == 0) *cntp = 0;

        // Issue tw[s] loads into registers FIRST; latency overlaps the scan.
        float4 twr[8];
        {
            const float4* src = (const float4*)(tw + (size_t)s * INPUT * INTER);
            #pragma unroll
            for (int i = 0; i < 8; i++) twr[i] = src[t + i * 256];
        }
        __syncthreads();   // cnt=0 visible before scan's atomicAdd

        for (int i = t; i < RPC; i += 256) {
            int rr = r0 + i;
            if (tc[rr] == s && mask[rr] != 0) {
                int pos = atomicAdd(cntp, 1);
                list[pos] = (dc[rr] << 16) | rr;
            }
        }
        {   // commit tw[s] (LDG latency absorbed by the scan)
            #pragma unroll
            for (int i = 0; i < 8; i++)
                ((float4*)tws)[t + i * 256] = twr[i];
        }
        __syncthreads();   // list + tws ready

        const int n    = *cntp;
        const int warp = t >> 5;
        const int lane = t & 31;
        const int j0   = lane * 2;
        float* xsw = (float*)(smem + SM_XS) + warp * 4 * INPUT;

        // 4-row groups: each weight k-block read feeds 4 rows.
        for (int i = warp * 4; i < n; i += 32) {
            const int m = n - i;   // rows in this group (>=1)
            const int e0 = list[i];
            const int e1 = (m > 1) ? list[i + 1] : e0;
            const int e2 = (m > 2) ? list[i + 2] : e0;
            const int e3 = (m > 3) ? list[i + 3] : e0;
            const int r0i = e0 & 0xFFFF, d0 = e0 >> 16;
            const int r1i = e1 & 0xFFFF, d1 = e1 >> 16;
            const int r2i = e2 & 0xFFFF, d2 = e2 >> 16;
            const int r3i = e3 & 0xFFFF, d3 = e3 >> 16;

            // Stage 4 rows: one coalesced LDG.128 per row per lane.
            __syncwarp();
            {
                const float4* x4 = (const float4*)x;
                float4 v0 = x4[(size_t)r0i * 32 + lane];
                float4 v1 = x4[(size_t)r1i * 32 + lane];
                float4 v2 = x4[(size_t)r2i * 32 + lane];
                float4 v3 = x4[(size_t)r3i * 32 + lane];
                *(float4*)(xsw + 0 * INPUT + lane * 4) = v0;
                *(float4*)(xsw + 1 * INPUT + lane * 4) = v1;
                *(float4*)(xsw + 2 * INPUT + lane * 4) = v2;
                *(float4*)(xsw + 3 * INPUT + lane * 4) = v3;
            }
            __syncwarp();

            float a00 = 0.f, a01 = 0.f, a10 = 0.f, a11 = 0.f;
            float a20 = 0.f, a21 = 0.f, a30 = 0.f, a31 = 0.f;
            #pragma unroll 4
            for (int k = 0; k < INPUT; k += 4) {
                float2 w0 = *(const float2*)(tws + (k + 0) * INTER + j0);
                float2 w1 = *(const float2*)(tws + (k + 1) * INTER + j0);
                float2 w2 = *(const float2*)(tws + (k + 2) * INTER + j0);
                float2 w3 = *(const float2*)(tws + (k + 3) * INTER + j0);
                float4 v0 = *(const float4*)(xsw + 0 * INPUT + k);
                float4 v1 = *(const float4*)(xsw + 1 * INPUT + k);
                float4 v2 = *(const float4*)(xsw + 2 * INPUT + k);
                float4 v3 = *(const float4*)(xsw + 3 * INPUT + k);
                a00 = fmaf(v0.x, w0.x, a00);  a01 = fmaf(v0.x, w0.y, a01);
                a10 = fmaf(v1.x, w0.x, a10);  a11 = fmaf(v1.x, w0.y, a11);
                a20 = fmaf(v2.x, w0.x, a20);  a21 = fmaf(v2.x, w0.y, a21);
                a30 = fmaf(v3.x, w0.x, a30);  a31 = fmaf(v3.x, w0.y, a31);
                a00 = fmaf(v0.y, w1.x, a00);  a01 = fmaf(v0.y, w1.y, a01);
                a10 = fmaf(v1.y, w1.x, a10);  a11 = fmaf(v1.y, w1.y, a11);
                a20 = fmaf(v2.y, w1.x, a20);  a21 = fmaf(v2.y, w1.y, a21);
                a30 = fmaf(v3.y, w1.x, a30);  a31 = fmaf(v3.y, w1.y, a31);
                a00 = fmaf(v0.z, w2.x, a00);  a01 = fmaf(v0.z, w2.y, a01);
                a10 = fmaf(v1.z, w2.x, a10);  a11 = fmaf(v1.z, w2.y, a11);
                a20 = fmaf(v2.z, w2.x, a20);  a21 = fmaf(v2.z, w2.y, a21);
                a30 = fmaf(v3.z, w2.x, a30);  a31 = fmaf(v3.z, w2.y, a31);
                a00 = fmaf(v0.w, w3.x, a00);  a01 = fmaf(v0.w, w3.y, a01);
                a10 = fmaf(v1.w, w3.x, a10);  a11 = fmaf(v1.w, w3.y, a11);
                a20 = fmaf(v2.w, w3.x, a20);  a21 = fmaf(v2.w, w3.y, a21);
                a30 = fmaf(v3.w, w3.x, a30);  a31 = fmaf(v3.w, w3.y, a31);
            }

            float* u0 = g_u + (size_t)(r0i / CDIM) * USTRIDE + d0 * INTER + j0;
            atomicAdd(u0, a00);  atomicAdd(u0 + 1, a01);
            if (m > 1) {
                float* u1 = g_u + (size_t)(r1i / CDIM) * USTRIDE + d1 * INTER + j0;
                atomicAdd(u1, a10);  atomicAdd(u1 + 1, a11);
            }
            if (m > 2) {
                float* u2 = g_u + (size_t)(r2i / CDIM) * USTRIDE + d2 * INTER + j0;
                atomicAdd(u2, a20);  atomicAdd(u2 + 1, a21);
            }
            if (m > 3) {
                float* u3 = g_u + (size_t)(r3i / CDIM) * USTRIDE + d3 * INTER + j0;
                atomicAdd(u3, a30);  atomicAdd(u3 + 1, a31);
            }
        }
    }
    __syncthreads();   // p1 smem readers done before ws/as overwrite

    // ===== Pre-barrier prefetch of phase-2 inputs =========================
    {
        const float* wsrc = (r < NSLOT)
            ? dw + (size_t)r * 64 * HIDDEN
            : hw + (size_t)(r - NSLOT) * 64 * HIDDEN;
        const float4* src = (const float4*)wsrc;
        #pragma unroll
        for (int i = 0; i < 8; i++)
            ((float4*)ws)[t + i * 256] = src[t + i * 256];
    }
    if (r >= NSLOT) {
        #pragma unroll
        for (int i = 0; i < 2; i++) {
            int idx = t + i * 256;
            int bb = idx >> 6, j = idx & 63;
            as[idx] = h[(size_t)(bbase + bb) * HIDDEN + (r - NSLOT) * 64 + j];
        }
    }

    // ======================= GRID BARRIER =================================
    // Safe: launch_bounds(256,3) + 50.8KB dyn smem (3x51 = 152KB < 228KB)
    // guarantee >=3 CTAs/SM; NB=416 <= 148*3 -> co-resident. Monotonic ctr.
    __syncthreads();
    if (t == 0) {
        __threadfence();
        unsigned c = atomicAdd(&g_bar, 1u);
        unsigned target = (c / NB + 1u) * NB;
        while (*(volatile unsigned*)&g_bar < target) __nanosleep(64);
        __threadfence();
    }
    __syncthreads();

    // ======================= PHASE 2: flat K-split GEMM ===================
    if (r < NSLOT) {
        #pragma unroll
        for (int i = 0; i < 2; i++) {
            int idx = t + i * 256;
            int bb = idx >> 6, j = idx & 63;
            float* up = g_u + (size_t)(bbase + bb) * USTRIDE + r * 64 + j;
            float v = *up;
            *up = 0.f;
            as[idx] = v;
        }
        __syncthreads();
    }

    const int bg  = t >> 7;
    const int hid = t & 127;

    float acc0 = 0.f, acc1 = 0.f, acc2 = 0.f, acc3 = 0.f;
    #pragma unroll
    for (int j = 0; j < 64; j += 4) {
        float w0 = ws[(j + 0) * HIDDEN + hid];
        float w1 = ws[(j + 1) * HIDDEN + hid];
        float w2 = ws[(j + 2) * HIDDEN + hid];
        float w3 = ws[(j + 3) * HIDDEN + hid];
        float4 a0 = *(const float4*)(as + (bg + 0) * 64 + j);
        float4 a1 = *(const float4*)(as + (bg + 2) * 64 + j);
        float4 a2 = *(const float4*)(as + (bg + 4) * 64 + j);
        float4 a3 = *(const float4*)(as + (bg + 6) * 64 + j);
        acc0 = fmaf(a0.x, w0, acc0);  acc1 = fmaf(a1.x, w0, acc1);
        acc2 = fmaf(a2.x, w0, acc2);  acc3 = fmaf(a3.x, w0, acc3);
        acc0 = fmaf(a0.y, w1, acc0);  acc1 = fmaf(a1.y, w1, acc1);
        acc2 = fmaf(a2.y, w1, acc2);  acc3 = fmaf(a3.y, w1, acc3);
        acc0 = fmaf(a0.z, w2, acc0);  acc1 = fmaf(a1.z, w2, acc1);
        acc2 = fmaf(a2.z, w2, acc2);  acc3 = fmaf(a3.z, w2, acc3);
        acc0 = fmaf(a0.w, w3, acc0);  acc1 = fmaf(a1.w, w3, acc1);
        acc2 = fmaf(a2.w, w3, acc2);  acc3 = fmaf(a3.w, w3, acc3);
    }

    atomicAdd(g_acc + (size_t)(bbase + bg + 0) * HIDDEN + hid, acc0);
    atomicAdd(g_acc + (size_t)(bbase + bg + 2) * HIDDEN + hid, acc1);
    atomicAdd(g_acc + (size_t)(bbase + bg + 4) * HIDDEN + hid, acc2);
    atomicAdd(g_acc + (size_t)(bbase + bg + 6) * HIDDEN + hid, acc3);

    __threadfence();
    __syncthreads();
    if (t == 0) {
        unsigned c = atomicAdd(&g_fin[bx], 1u);
        flag = ((c % (unsigned)NROUND) == (unsigned)(NROUND - 1)) ? 1 : 0;
    }
    __syncthreads();

    if (flag) {
        #pragma unroll
        for (int i = 0; i < 4; i++) {
            float* p = g_acc + (size_t)(bbase + bg + 2 * i) * HIDDEN + hid;
            float v = __ldcg(p);
            out[(size_t)(bbase + bg + 2 * i) * HIDDEN + hid] =
                1.f / (1.f + expf(-v));
            *p = 0.f;
        }
    }
}

// ---------------------------------------------------------------------------
// kernel_launch: ONE launch, dynamic smem >48KB via attribute opt-in.
// cudaFuncSetAttribute is an attribute set (no allocation) and is called on
// every invocation -- capture-safe and idempotent.
// ---------------------------------------------------------------------------
extern "C" void kernel_launch(void* const* d_in, const int* in_sizes, int n_in,
                              void* d_out, int out_size) {
    const float* x    = (const float*)d_in[0];
    const int*   tc   = (const int*)d_in[1];
    const int*   dc   = (const int*)d_in[2];
    const int*   mask = (const int*)d_in[3];
    const float* h    = (const float*)d_in[4];
    const float* tw   = (const float*)d_in[5];
    const float* dw   = (const float*)d_in[6];
    const float* hw   = (const float*)d_in[7];
    float*       out  = (float*)d_out;

    cudaFuncSetAttribute(fused_kernel,
                         cudaFuncAttributeMaxDynamicSharedMemorySize,
                         SMEM_TOTAL);
    fused_kernel<<<NB, 256, SMEM_TOTAL>>>(x, tc, dc, mask, h, tw, dw, hw, out);
}

// round 15
// speedup vs baseline: 1.2051x; 1.0283x over previous
#include <cuda_runtime.h>
#include <math.h>

#define NROWS   12800     // B*C
#define BATCH   256
#define CDIM    50
#define INPUT   128
#define INTER   64
#define HIDDEN  128
#define NSLOT   11
#define USTRIDE (NSLOT * INTER)      // 704
#define NCHUNK  32
#define RPC     (NROWS / NCHUNK)     // 400 rows per chunk = batches [8bx, 8bx+8)
#define NROUND  13                   // 11 dw slots + 2 hw halves
#define BPG     8                    // batches per chunk / stage2 CTA-group
#define NB      (NCHUNK * NROUND)    // 416 CTAs (<= 148 SMs x 3 -> co-resident)

// Dynamic smem layout (bytes):
//   phase 1:  [0,32768) tws   [32768,49152) xs (8 warps x 4 rows x 128 f)
//             [49152,50752) list[400]   [50752,50756) cnt
//   phase 2:  [0,32768) ws    [32768,34816) as
#define SM_TWS   0
#define SM_XS    32768
#define SM_LIST  49152
#define SM_CNT   50752
#define SM_WS    0
#define SM_AS    32768
#define SMEM_TOTAL 50768

__device__ float g_u[BATCH * USTRIDE];   // zero-init; phase2 rezeroes after read
__device__ float g_acc[BATCH * HIDDEN];  // zero-init; finisher rezeroes
__device__ unsigned g_done[NCHUNK];      // per-chunk barrier tickets (monotonic)
__device__ unsigned g_fin[NCHUNK];       // finisher counters (monotonic)

__global__ __launch_bounds__(256, 3) void fused_kernel(
    const float* __restrict__ x,     // (B,C,INPUT)
    const int* __restrict__ tc,      // (B,C)
    const int* __restrict__ dc,      // (B,C)
    const int* __restrict__ mask,    // (B,C) bool->int32
    const float* __restrict__ h,     // (B,HIDDEN)
    const float* __restrict__ tw,    // (NSLOT,INPUT,INTER)
    const float* __restrict__ dw,    // (NSLOT,INTER,HIDDEN)
    const float* __restrict__ hw,    // (HIDDEN,HIDDEN)
    float* __restrict__ out)         // (B,HIDDEN)
{
    extern __shared__ __align__(16) char smem[];
    float* tws  = (float*)(smem + SM_TWS);
    int*   list = (int*)(smem + SM_LIST);
    int*   cntp = (int*)(smem + SM_CNT);
    float* ws   = (float*)(smem + SM_WS);
    float* as   = (float*)(smem + SM_AS);
    __shared__ int flag;
    __shared__ unsigned ticket;

    const int id  = blockIdx.x;            // 0..415
    const int t   = threadIdx.x;
    const int bx  = id & 31;               // chunk / phase2 batch group
    const int r   = id >> 5;               // phase2 k-round; == slot s in phase1
    const int bbase = bx * BPG;

    // ======================= PHASE 1: x @ tw[s] ===========================
    if (r < NSLOT) {
        const int s  = r;
        const int r0 = bx * RPC;

        if (t == 0) *cntp = 0;

        // Issue tw[s] loads into registers FIRST; latency overlaps the scan.
        float4 twr[8];
        {
            const float4* src = (const float4*)(tw + (size_t)s * INPUT * INTER);
            #pragma unroll
            for (int i = 0; i < 8; i++) twr[i] = src[t + i * 256];
        }
        __syncthreads();   // cnt=0 visible before scan's atomicAdd

        for (int i = t; i < RPC; i += 256) {
            int rr = r0 + i;
            if (tc[rr] == s && mask[rr] != 0) {
                int pos = atomicAdd(cntp, 1);
                list[pos] = (dc[rr] << 16) | rr;
            }
        }
        {   // commit tw[s] (LDG latency absorbed by the scan)
            #pragma unroll
            for (int i = 0; i < 8; i++)
                ((float4*)tws)[t + i * 256] = twr[i];
        }
        __syncthreads();   // list + tws ready

        const int n    = *cntp;
        const int warp = t >> 5;
        const int lane = t & 31;
        const int j0   = lane * 2;
        float* xsw = (float*)(smem + SM_XS) + warp * 4 * INPUT;

        // 4-row groups: each weight k-block read feeds 4 rows.
        for (int i = warp * 4; i < n; i += 32) {
            const int m = n - i;   // rows in this group (>=1)
            const int e0 = list[i];
            const int e1 = (m > 1) ? list[i + 1] : e0;
            const int e2 = (m > 2) ? list[i + 2] : e0;
            const int e3 = (m > 3) ? list[i + 3] : e0;
            const int r0i = e0 & 0xFFFF, d0 = e0 >> 16;
            const int r1i = e1 & 0xFFFF, d1 = e1 >> 16;
            const int r2i = e2 & 0xFFFF, d2 = e2 >> 16;
            const int r3i = e3 & 0xFFFF, d3 = e3 >> 16;

            // Stage 4 rows: one coalesced LDG.128 per row per lane.
            __syncwarp();
            {
                const float4* x4 = (const float4*)x;
                float4 v0 = x4[(size_t)r0i * 32 + lane];
                float4 v1 = x4[(size_t)r1i * 32 + lane];
                float4 v2 = x4[(size_t)r2i * 32 + lane];
                float4 v3 = x4[(size_t)r3i * 32 + lane];
                *(float4*)(xsw + 0 * INPUT + lane * 4) = v0;
                *(float4*)(xsw + 1 * INPUT + lane * 4) = v1;
                *(float4*)(xsw + 2 * INPUT + lane * 4) = v2;
                *(float4*)(xsw + 3 * INPUT + lane * 4) = v3;
            }
            __syncwarp();

            float a00 = 0.f, a01 = 0.f, a10 = 0.f, a11 = 0.f;
            float a20 = 0.f, a21 = 0.f, a30 = 0.f, a31 = 0.f;
            #pragma unroll 4
            for (int k = 0; k < INPUT; k += 4) {
                float2 w0 = *(const float2*)(tws + (k + 0) * INTER + j0);
                float2 w1 = *(const float2*)(tws + (k + 1) * INTER + j0);
                float2 w2 = *(const float2*)(tws + (k + 2) * INTER + j0);
                float2 w3 = *(const float2*)(tws + (k + 3) * INTER + j0);
                float4 v0 = *(const float4*)(xsw + 0 * INPUT + k);
                float4 v1 = *(const float4*)(xsw + 1 * INPUT + k);
                float4 v2 = *(const float4*)(xsw + 2 * INPUT + k);
                float4 v3 = *(const float4*)(xsw + 3 * INPUT + k);
                a00 = fmaf(v0.x, w0.x, a00);  a01 = fmaf(v0.x, w0.y, a01);
                a10 = fmaf(v1.x, w0.x, a10);  a11 = fmaf(v1.x, w0.y, a11);
                a20 = fmaf(v2.x, w0.x, a20);  a21 = fmaf(v2.x, w0.y, a21);
                a30 = fmaf(v3.x, w0.x, a30);  a31 = fmaf(v3.x, w0.y, a31);
                a00 = fmaf(v0.y, w1.x, a00);  a01 = fmaf(v0.y, w1.y, a01);
                a10 = fmaf(v1.y, w1.x, a10);  a11 = fmaf(v1.y, w1.y, a11);
                a20 = fmaf(v2.y, w1.x, a20);  a21 = fmaf(v2.y, w1.y, a21);
                a30 = fmaf(v3.y, w1.x, a30);  a31 = fmaf(v3.y, w1.y, a31);
                a00 = fmaf(v0.z, w2.x, a00);  a01 = fmaf(v0.z, w2.y, a01);
                a10 = fmaf(v1.z, w2.x, a10);  a11 = fmaf(v1.z, w2.y, a11);
                a20 = fmaf(v2.z, w2.x, a20);  a21 = fmaf(v2.z, w2.y, a21);
                a30 = fmaf(v3.z, w2.x, a30);  a31 = fmaf(v3.z, w2.y, a31);
                a00 = fmaf(v0.w, w3.x, a00);  a01 = fmaf(v0.w, w3.y, a01);
                a10 = fmaf(v1.w, w3.x, a10);  a11 = fmaf(v1.w, w3.y, a11);
                a20 = fmaf(v2.w, w3.x, a20);  a21 = fmaf(v2.w, w3.y, a21);
                a30 = fmaf(v3.w, w3.x, a30);  a31 = fmaf(v3.w, w3.y, a31);
            }

            float* u0 = g_u + (size_t)(r0i / CDIM) * USTRIDE + d0 * INTER + j0;
            atomicAdd(u0, a00);  atomicAdd(u0 + 1, a01);
            if (m > 1) {
                float* u1 = g_u + (size_t)(r1i / CDIM) * USTRIDE + d1 * INTER + j0;
                atomicAdd(u1, a10);  atomicAdd(u1 + 1, a11);
            }
            if (m > 2) {
                float* u2 = g_u + (size_t)(r2i / CDIM) * USTRIDE + d2 * INTER + j0;
                atomicAdd(u2, a20);  atomicAdd(u2 + 1, a21);
            }
            if (m > 3) {
                float* u3 = g_u + (size_t)(r3i / CDIM) * USTRIDE + d3 * INTER + j0;
                atomicAdd(u3, a30);  atomicAdd(u3 + 1, a31);
            }
        }
    }
    __syncthreads();   // all warps' atomics issued; p1 smem readers done

    // ====== PER-CHUNK BARRIER, part 1: ARRIVE (before prefetch) ===========
    // Phase-2 CTA (bx, r) only depends on the 11 phase-1 CTAs with the same
    // chunk bx (chunk bx == batches [8bx, 8bx+8) exactly). All 13 CTAs of a
    // chunk arrive; wait target is epoch-monotonic -> replay-safe.
    if (t == 0) {
        __threadfence();   // publish this CTA's g_u atomics before arrival
        ticket = atomicAdd(&g_done[bx], 1u);
    }

    // ===== Prefetch of phase-2 inputs (overlaps other CTAs' phase 1) ======
    {
        const float* wsrc = (r < NSLOT)
            ? dw + (size_t)r * 64 * HIDDEN
            : hw + (size_t)(r - NSLOT) * 64 * HIDDEN;
        const float4* src = (const float4*)wsrc;
        #pragma unroll
        for (int i = 0; i < 8; i++)
            ((float4*)ws)[t + i * 256] = src[t + i * 256];
    }
    if (r >= NSLOT) {
        #pragma unroll
        for (int i = 0; i < 2; i++) {
            int idx = t + i * 256;
            int bb = idx >> 6, j = idx & 63;
            as[idx] = h[(size_t)(bbase + bb) * HIDDEN + (r - NSLOT) * 64 + j];
        }
    }

    // ====== PER-CHUNK BARRIER, part 2: WAIT ===============================
    __syncthreads();   // ticket visible; prefetch stores issued
    if (t == 0) {
        unsigned target = (ticket / (unsigned)NROUND + 1u) * (unsigned)NROUND;
        while (*(volatile unsigned*)&g_done[bx] < target) __nanosleep(32);
        __threadfence();
    }
    __syncthreads();

    // ======================= PHASE 2: flat K-split GEMM ===================
    if (r < NSLOT) {
        #pragma unroll
        for (int i = 0; i < 2; i++) {
            int idx = t + i * 256;
            int bb = idx >> 6, j = idx & 63;
            float* up = g_u + (size_t)(bbase + bb) * USTRIDE + r * 64 + j;
            float v = *up;
            *up = 0.f;
            as[idx] = v;
        }
        __syncthreads();
    }

    const int bg  = t >> 7;
    const int hid = t & 127;

    float acc0 = 0.f, acc1 = 0.f, acc2 = 0.f, acc3 = 0.f;
    #pragma unroll
    for (int j = 0; j < 64; j += 4) {
        float w0 = ws[(j + 0) * HIDDEN + hid];
        float w1 = ws[(j + 1) * HIDDEN + hid];
        float w2 = ws[(j + 2) * HIDDEN + hid];
        float w3 = ws[(j + 3) * HIDDEN + hid];
        float4 a0 = *(const float4*)(as + (bg + 0) * 64 + j);
        float4 a1 = *(const float4*)(as + (bg + 2) * 64 + j);
        float4 a2 = *(const float4*)(as + (bg + 4) * 64 + j);
        float4 a3 = *(const float4*)(as + (bg + 6) * 64 + j);
        acc0 = fmaf(a0.x, w0, acc0);  acc1 = fmaf(a1.x, w0, acc1);
        acc2 = fmaf(a2.x, w0, acc2);  acc3 = fmaf(a3.x, w0, acc3);
        acc0 = fmaf(a0.y, w1, acc0);  acc1 = fmaf(a1.y, w1, acc1);
        acc2 = fmaf(a2.y, w1, acc2);  acc3 = fmaf(a3.y, w1, acc3);
        acc0 = fmaf(a0.z, w2, acc0);  acc1 = fmaf(a1.z, w2, acc1);
        acc2 = fmaf(a2.z, w2, acc2);  acc3 = fmaf(a3.z, w2, acc3);
        acc0 = fmaf(a0.w, w3, acc0);  acc1 = fmaf(a1.w, w3, acc1);
        acc2 = fmaf(a2.w, w3, acc2);  acc3 = fmaf(a3.w, w3, acc3);
    }

    atomicAdd(g_acc + (size_t)(bbase + bg + 0) * HIDDEN + hid, acc0);
    atomicAdd(g_acc + (size_t)(bbase + bg + 2) * HIDDEN + hid, acc1);
    atomicAdd(g_acc + (size_t)(bbase + bg + 4) * HIDDEN + hid, acc2);
    atomicAdd(g_acc + (size_t)(bbase + bg + 6) * HIDDEN + hid, acc3);

    __threadfence();
    __syncthreads();
    if (t == 0) {
        unsigned c = atomicAdd(&g_fin[bx], 1u);
        flag = ((c % (unsigned)NROUND) == (unsigned)(NROUND - 1)) ? 1 : 0;
    }
    __syncthreads();

    if (flag) {
        #pragma unroll
        for (int i = 0; i < 4; i++) {
            float* p = g_acc + (size_t)(bbase + bg + 2 * i) * HIDDEN + hid;
            float v = __ldcg(p);
            out[(size_t)(bbase + bg + 2 * i) * HIDDEN + hid] =
                1.f / (1.f + expf(-v));
            *p = 0.f;
        }
    }
}

// ---------------------------------------------------------------------------
// kernel_launch: ONE launch, dynamic smem >48KB via attribute opt-in.
// ---------------------------------------------------------------------------
extern "C" void kernel_launch(void* const* d_in, const int* in_sizes, int n_in,
                              void* d_out, int out_size) {
    const float* x    = (const float*)d_in[0];
    const int*   tc   = (const int*)d_in[1];
    const int*   dc   = (const int*)d_in[2];
    const int*   mask = (const int*)d_in[3];
    const float* h    = (const float*)d_in[4];
    const float* tw   = (const float*)d_in[5];
    const float* dw   = (const float*)d_in[6];
    const float* hw   = (const float*)d_in[7];
    float*       out  = (float*)d_out;

    cudaFuncSetAttribute(fused_kernel,
                         cudaFuncAttributeMaxDynamicSharedMemorySize,
                         SMEM_TOTAL);
    fused_kernel<<<NB, 256, SMEM_TOTAL>>>(x, tc, dc, mask, h, tw, dw, hw, out);
}